// round 7
// baseline (speedup 1.0000x reference)
#include <cuda_runtime.h>

// VDDecoder: 3-layer LSTM stack (H=2,2,1), locked dropout between layers.
// One thread per batch element; layers software-pipelined with 1-step stagger.
// f32x2-packed gate math; tanh.approx activations with 0.5-prescaled sigmoid
// rows. R7: launch as block=256/grid=32 to pack 2 warps per SMSP so the
// co-resident warp fills dependency-stall cycles (R6 ran 1 warp/SMSP at 23%
// issue).

typedef unsigned long long u64;

__device__ __forceinline__ float ftanh(float x) {
    float r; asm("tanh.approx.f32 %0, %1;" : "=f"(r) : "f"(x)); return r;
}
__device__ __forceinline__ u64 fpack(float lo, float hi) {
    u64 d; asm("mov.b64 %0, {%1, %2};" : "=l"(d) : "f"(lo), "f"(hi)); return d;
}
__device__ __forceinline__ void funpack(u64 v, float& lo, float& hi) {
    asm("mov.b64 {%0, %1}, %2;" : "=f"(lo), "=f"(hi) : "l"(v));
}
__device__ __forceinline__ u64 ffma2(u64 a, u64 b, u64 c) {
    u64 d; asm("fma.rn.f32x2 %0, %1, %2, %3;" : "=l"(d) : "l"(a), "l"(b), "l"(c)); return d;
}
__device__ __forceinline__ u64 fmul2(u64 a, u64 b) {
    u64 d; asm("mul.rn.f32x2 %0, %1, %2;" : "=l"(d) : "l"(a), "l"(b)); return d;
}

extern "C" __global__ void __launch_bounds__(256, 1)
vdlstm_v3_kernel(const float* __restrict__ x,
                 const float* __restrict__ W1ih, const float* __restrict__ W1hh,
                 const float* __restrict__ b1,   const float* __restrict__ m1,
                 const float* __restrict__ W2ih, const float* __restrict__ W2hh,
                 const float* __restrict__ b2,   const float* __restrict__ m2,
                 const float* __restrict__ W3ih, const float* __restrict__ W3hh,
                 const float* __restrict__ b3,   const float* __restrict__ m3,
                 float* __restrict__ out, int T, int B)
{
    int b = blockIdx.x * blockDim.x + threadIdx.x;
    if (b >= B) return;

    const float m10 = m1[2 * b + 0], m11 = m1[2 * b + 1];
    const float m20 = m2[2 * b + 0], m21 = m2[2 * b + 1];
    const float m30 = m3[b];

    const u64 H2 = fpack(0.5f, 0.5f);

    // ---- packed weights; gate-pair p covers rows (2p, 2p+1) ----
    // torch order: p=0 -> i, p=1 -> f, p=2 -> g (tanh, unscaled), p=3 -> o
    u64 P1wi[4], P1wh0[4], P1wh1[4], P1b[4];
#pragma unroll
    for (int p = 0; p < 4; p++) {
        float s = (p == 2) ? 1.0f : 0.5f;
        int r0 = 2 * p, r1 = 2 * p + 1;
        P1wi[p]  = fpack(W1ih[r0] * s,          W1ih[r1] * s);
        P1wh0[p] = fpack(W1hh[2 * r0 + 0] * s,  W1hh[2 * r1 + 0] * s);
        P1wh1[p] = fpack(W1hh[2 * r0 + 1] * s,  W1hh[2 * r1 + 1] * s);
        P1b[p]   = fpack(b1[r0] * s,            b1[r1] * s);
    }
    u64 P2wi0[4], P2wi1[4], P2wh0[4], P2wh1[4], P2b[4];
#pragma unroll
    for (int p = 0; p < 4; p++) {
        float s = (p == 2) ? 1.0f : 0.5f;
        int r0 = 2 * p, r1 = 2 * p + 1;
        P2wi0[p] = fpack(W2ih[2 * r0 + 0] * s * m10, W2ih[2 * r1 + 0] * s * m10);
        P2wi1[p] = fpack(W2ih[2 * r0 + 1] * s * m11, W2ih[2 * r1 + 1] * s * m11);
        P2wh0[p] = fpack(W2hh[2 * r0 + 0] * s,       W2hh[2 * r1 + 0] * s);
        P2wh1[p] = fpack(W2hh[2 * r0 + 1] * s,       W2hh[2 * r1 + 1] * s);
        P2b[p]   = fpack(b2[r0] * s,                 b2[r1] * s);
    }
    // layer3 (H=1): rows 0=i(.5) 1=f(.5) 2=g(1) 3=o(.5); pairs A=(i,f), B=(g,o)
    u64 P3wi0A = fpack(W3ih[0] * 0.5f * m20, W3ih[2] * 0.5f * m20);
    u64 P3wi1A = fpack(W3ih[1] * 0.5f * m21, W3ih[3] * 0.5f * m21);
    u64 P3whA  = fpack(W3hh[0] * 0.5f,       W3hh[1] * 0.5f);
    u64 P3bA   = fpack(b3[0] * 0.5f,         b3[1] * 0.5f);
    u64 P3wi0B = fpack(W3ih[4] * m20,        W3ih[6] * 0.5f * m20);
    u64 P3wi1B = fpack(W3ih[5] * m21,        W3ih[7] * 0.5f * m21);
    u64 P3whB  = fpack(W3hh[2],              W3hh[3] * 0.5f);
    u64 P3bB   = fpack(b3[2],                b3[3] * 0.5f);

    // ---- state ----
    float h10 = 0.f, h11 = 0.f;  u64 cp1 = fpack(0.f, 0.f);
    float h20 = 0.f, h21 = 0.f;  u64 cp2 = fpack(0.f, 0.f);
    float h3 = 0.f,  c3 = 0.f;

    auto step1 = [&](float xt) {
        u64 x2  = fpack(xt, xt);
        u64 h0b = fpack(h10, h10), h1b = fpack(h11, h11);
        u64 gI = ffma2(x2, P1wi[0], ffma2(h0b, P1wh0[0], ffma2(h1b, P1wh1[0], P1b[0])));
        u64 gF = ffma2(x2, P1wi[1], ffma2(h0b, P1wh0[1], ffma2(h1b, P1wh1[1], P1b[1])));
        u64 gG = ffma2(x2, P1wi[2], ffma2(h0b, P1wh0[2], ffma2(h1b, P1wh1[2], P1b[2])));
        u64 gO = ffma2(x2, P1wi[3], ffma2(h0b, P1wh0[3], ffma2(h1b, P1wh1[3], P1b[3])));
        float a0, a1;
        funpack(gI, a0, a1); u64 tI = fpack(ftanh(a0), ftanh(a1));
        funpack(gF, a0, a1); u64 tF = fpack(ftanh(a0), ftanh(a1));
        funpack(gG, a0, a1); u64 tG = fpack(ftanh(a0), ftanh(a1));
        funpack(gO, a0, a1); u64 tO = fpack(ftanh(a0), ftanh(a1));
        u64 iP = ffma2(tI, H2, H2);
        u64 fP = ffma2(tF, H2, H2);
        u64 oP = ffma2(tO, H2, H2);
        cp1 = ffma2(fP, cp1, fmul2(iP, tG));
        funpack(cp1, a0, a1);
        u64 tC = fpack(ftanh(a0), ftanh(a1));
        u64 hP = fmul2(oP, tC);
        funpack(hP, h10, h11);
    };

    auto step2 = [&](float a0s, float a1s) {   // a = raw h1 (m1 folded into P2wi*)
        u64 a0b = fpack(a0s, a0s), a1b = fpack(a1s, a1s);
        u64 h0b = fpack(h20, h20), h1b = fpack(h21, h21);
        u64 gI = ffma2(a0b, P2wi0[0], ffma2(a1b, P2wi1[0], ffma2(h0b, P2wh0[0], ffma2(h1b, P2wh1[0], P2b[0]))));
        u64 gF = ffma2(a0b, P2wi0[1], ffma2(a1b, P2wi1[1], ffma2(h0b, P2wh0[1], ffma2(h1b, P2wh1[1], P2b[1]))));
        u64 gG = ffma2(a0b, P2wi0[2], ffma2(a1b, P2wi1[2], ffma2(h0b, P2wh0[2], ffma2(h1b, P2wh1[2], P2b[2]))));
        u64 gO = ffma2(a0b, P2wi0[3], ffma2(a1b, P2wi1[3], ffma2(h0b, P2wh0[3], ffma2(h1b, P2wh1[3], P2b[3]))));
        float a0, a1;
        funpack(gI, a0, a1); u64 tI = fpack(ftanh(a0), ftanh(a1));
        funpack(gF, a0, a1); u64 tF = fpack(ftanh(a0), ftanh(a1));
        funpack(gG, a0, a1); u64 tG = fpack(ftanh(a0), ftanh(a1));
        funpack(gO, a0, a1); u64 tO = fpack(ftanh(a0), ftanh(a1));
        u64 iP = ffma2(tI, H2, H2);
        u64 fP = ffma2(tF, H2, H2);
        u64 oP = ffma2(tO, H2, H2);
        cp2 = ffma2(fP, cp2, fmul2(iP, tG));
        funpack(cp2, a0, a1);
        u64 tC = fpack(ftanh(a0), ftanh(a1));
        u64 hP = fmul2(oP, tC);
        funpack(hP, h20, h21);
    };

    auto step3 = [&](float a0s, float a1s) -> float {   // a = raw h2 (m2 folded)
        u64 a0b = fpack(a0s, a0s), a1b = fpack(a1s, a1s);
        u64 h3b = fpack(h3, h3);
        u64 gA = ffma2(a0b, P3wi0A, ffma2(a1b, P3wi1A, ffma2(h3b, P3whA, P3bA)));
        u64 gB = ffma2(a0b, P3wi0B, ffma2(a1b, P3wi1B, ffma2(h3b, P3whB, P3bB)));
        float vi, vf, vg, vo;
        funpack(gA, vi, vf);
        funpack(gB, vg, vo);
        float si = fmaf(ftanh(vi), 0.5f, 0.5f);
        float sf = fmaf(ftanh(vf), 0.5f, 0.5f);
        float tg = ftanh(vg);
        float so = fmaf(ftanh(vo), 0.5f, 0.5f);
        c3 = fmaf(sf, c3, si * tg);
        h3 = so * ftanh(c3);
        return h3 * m30;
    };

    const float* xp = x + b;
    float* op = out + b;
    const long long Bs = (long long)B;

    // ---- pipeline prologue ----
    step1(xp[0]);
    {
        float p0 = h10, p1 = h11;
        step1(xp[Bs]);
        step2(p0, p1);
    }

    // ---- steady state: u = 2 .. T-1; layer1(u), layer2(u-1), layer3(u-2) ----
    float xa = xp[2 * Bs], xb = xp[3 * Bs], xc = xp[4 * Bs], xd = xp[5 * Bs];

#define PIPE_SUB(XREG, OFF, ROFF)                                              \
    {                                                                          \
        float p10 = h10, p11 = h11, p20 = h20, p21 = h21;                      \
        float nx = ((u + (ROFF)) < T) ? xp[(long long)(u + (ROFF)) * Bs] : 0.f;\
        step1(XREG);                                                           \
        step2(p10, p11);                                                       \
        op[(long long)(u + (OFF) - 2) * Bs] = step3(p20, p21);                 \
        XREG = nx;                                                             \
    }

    int u = 2;
    for (; u + 3 < T; u += 4) {
        PIPE_SUB(xa, 0, 4)
        PIPE_SUB(xb, 1, 5)
        PIPE_SUB(xc, 2, 6)
        PIPE_SUB(xd, 3, 7)
    }
    for (; u < T; ++u) {
        float p10 = h10, p11 = h11, p20 = h20, p21 = h21;
        step1(xa);
        step2(p10, p11);
        op[(long long)(u - 2) * Bs] = step3(p20, p21);
        xa = xb; xb = xc; xc = xd;
    }
#undef PIPE_SUB

    // ---- epilogue ----
    {
        float p20 = h20, p21 = h21;        // h2(T-2)
        step2(h10, h11);                   // h2(T-1)
        op[(long long)(T - 2) * Bs] = step3(p20, p21);
    }
    op[(long long)(T - 1) * Bs] = step3(h20, h21);
}

extern "C" void kernel_launch(void* const* d_in, const int* in_sizes, int n_in,
                              void* d_out, int out_size)
{
    const float* x    = (const float*)d_in[0];
    const float* W1ih = (const float*)d_in[1];
    const float* W1hh = (const float*)d_in[2];
    const float* b1   = (const float*)d_in[3];
    const float* m1   = (const float*)d_in[4];
    const float* W2ih = (const float*)d_in[5];
    const float* W2hh = (const float*)d_in[6];
    const float* b2   = (const float*)d_in[7];
    const float* m2   = (const float*)d_in[8];
    const float* W3ih = (const float*)d_in[9];
    const float* W3hh = (const float*)d_in[10];
    const float* b3   = (const float*)d_in[11];
    const float* m3   = (const float*)d_in[12];

    int B = in_sizes[12];            // m3 is [B]
    int T = in_sizes[0] / B;         // x is [T, B, 1]

    // 2 warps per SMSP: 256-thread blocks -> 8 warps -> 2 per SMSP (wid%4);
    // grid = B/256 = 32 blocks, one per SM.
    int threads = 256;
    int blocks = (B + threads - 1) / threads;
    vdlstm_v3_kernel<<<blocks, threads>>>(x, W1ih, W1hh, b1, m1,
                                          W2ih, W2hh, b2, m2,
                                          W3ih, W3hh, b3, m3,
                                          (float*)d_out, T, B);
}

// round 8
// speedup vs baseline: 1.1725x; 1.1725x over previous
#include <cuda_runtime.h>

// VDDecoder: 3-layer LSTM stack (H=2,2,1), locked dropout between layers.
// Lane-pair split: even lane = layer1, odd lane = layer2, SAME instruction
// stream (uniform H=2 2-input LSTM; only register weight values differ per
// lane). h1/h2 exchanged with shfl.xor(1) — no barriers. Layer3 (H=1) is
// computed redundantly by both lanes (keeps stream uniform); even lane stores.
// 2*B = 16384 threads = 512 warps -> ~512 SMSPs at 1 warp each.
// f32x2 packed math; tanh.approx activations, sigmoid rows 0.5-prescaled.

typedef unsigned long long u64;

__device__ __forceinline__ float ftanh(float x) {
    float r; asm("tanh.approx.f32 %0, %1;" : "=f"(r) : "f"(x)); return r;
}
__device__ __forceinline__ u64 fpack(float lo, float hi) {
    u64 d; asm("mov.b64 %0, {%1, %2};" : "=l"(d) : "f"(lo), "f"(hi)); return d;
}
__device__ __forceinline__ void funpack(u64 v, float& lo, float& hi) {
    asm("mov.b64 {%0, %1}, %2;" : "=f"(lo), "=f"(hi) : "l"(v));
}
__device__ __forceinline__ u64 ffma2(u64 a, u64 b, u64 c) {
    u64 d; asm("fma.rn.f32x2 %0, %1, %2, %3;" : "=l"(d) : "l"(a), "l"(b), "l"(c)); return d;
}
__device__ __forceinline__ u64 fmul2(u64 a, u64 b) {
    u64 d; asm("mul.rn.f32x2 %0, %1, %2;" : "=l"(d) : "l"(a), "l"(b)); return d;
}

extern "C" __global__ void __launch_bounds__(128, 1)
vdlstm_v4_kernel(const float* __restrict__ x,
                 const float* __restrict__ W1ih, const float* __restrict__ W1hh,
                 const float* __restrict__ b1,   const float* __restrict__ m1,
                 const float* __restrict__ W2ih, const float* __restrict__ W2hh,
                 const float* __restrict__ b2,   const float* __restrict__ m2,
                 const float* __restrict__ W3ih, const float* __restrict__ W3hh,
                 const float* __restrict__ b3,   const float* __restrict__ m3,
                 float* __restrict__ out, int T, int B)
{
    const int tid  = threadIdx.x;
    const int role = tid & 1;                       // 0 = layer1 lane, 1 = layer2 lane
    const int e    = blockIdx.x * (blockDim.x >> 1) + (tid >> 1);
    if (e >= B) return;

    const u64 H2 = fpack(0.5f, 0.5f);

    // ---- uniform main-LSTM weights (H=2, inputs a0,a1); values differ per role ----
    // gate-pair p covers torch rows (2p,2p+1): p=0 i, 1 f, 2 g(tanh), 3 o.
    u64 Wi0[4], Wi1[4], Wh0[4], Wh1[4], Bb[4];
    if (role == 0) {   // layer1: 1 input (a0 = x, a1 unused via zero weights)
#pragma unroll
        for (int p = 0; p < 4; p++) {
            float s = (p == 2) ? 1.0f : 0.5f;
            int r0 = 2 * p, r1 = 2 * p + 1;
            Wi0[p] = fpack(W1ih[r0] * s,          W1ih[r1] * s);
            Wi1[p] = fpack(0.f, 0.f);
            Wh0[p] = fpack(W1hh[2 * r0 + 0] * s,  W1hh[2 * r1 + 0] * s);
            Wh1[p] = fpack(W1hh[2 * r0 + 1] * s,  W1hh[2 * r1 + 1] * s);
            Bb[p]  = fpack(b1[r0] * s,            b1[r1] * s);
        }
    } else {           // layer2: inputs = raw h1 (m1 folded into input columns)
        float m10 = m1[2 * e + 0], m11 = m1[2 * e + 1];
#pragma unroll
        for (int p = 0; p < 4; p++) {
            float s = (p == 2) ? 1.0f : 0.5f;
            int r0 = 2 * p, r1 = 2 * p + 1;
            Wi0[p] = fpack(W2ih[2 * r0 + 0] * s * m10, W2ih[2 * r1 + 0] * s * m10);
            Wi1[p] = fpack(W2ih[2 * r0 + 1] * s * m11, W2ih[2 * r1 + 1] * s * m11);
            Wh0[p] = fpack(W2hh[2 * r0 + 0] * s,       W2hh[2 * r1 + 0] * s);
            Wh1[p] = fpack(W2hh[2 * r0 + 1] * s,       W2hh[2 * r1 + 1] * s);
            Bb[p]  = fpack(b2[r0] * s,                 b2[r1] * s);
        }
    }

    // ---- layer3 weights (identical on both lanes; m2 folded) ----
    const float m20 = m2[2 * e + 0], m21 = m2[2 * e + 1];
    const float m30 = m3[e];
    u64 P3wi0A = fpack(W3ih[0] * 0.5f * m20, W3ih[2] * 0.5f * m20);
    u64 P3wi1A = fpack(W3ih[1] * 0.5f * m21, W3ih[3] * 0.5f * m21);
    u64 P3whA  = fpack(W3hh[0] * 0.5f,       W3hh[1] * 0.5f);
    u64 P3bA   = fpack(b3[0] * 0.5f,         b3[1] * 0.5f);
    u64 P3wi0B = fpack(W3ih[4] * m20,        W3ih[6] * 0.5f * m20);
    u64 P3wi1B = fpack(W3ih[5] * m21,        W3ih[7] * 0.5f * m21);
    u64 P3whB  = fpack(W3hh[2],              W3hh[3] * 0.5f);
    u64 P3bB   = fpack(b3[2],                b3[3] * 0.5f);

    // ---- state ----
    float hm0 = 0.f, hm1 = 0.f;  u64 cm = fpack(0.f, 0.f);   // this lane's layer state
    float h3 = 0.f,  c3 = 0.f;                               // layer3 (redundant)
    float p20 = 0.f, p21 = 0.f;                              // delayed h2 (layer3 input)
    float rin0 = 0.f, rin1 = 0.f;                            // received partner h-pair

    // uniform main step: returns new h pair, outputs new c pair (no commit)
    auto stepM = [&](float a0, float a1, u64& cn) -> u64 {
        u64 a0b = fpack(a0, a0), a1b = fpack(a1, a1);
        u64 h0b = fpack(hm0, hm0), h1b = fpack(hm1, hm1);
        u64 gI = ffma2(a0b, Wi0[0], ffma2(a1b, Wi1[0], ffma2(h0b, Wh0[0], ffma2(h1b, Wh1[0], Bb[0]))));
        u64 gF = ffma2(a0b, Wi0[1], ffma2(a1b, Wi1[1], ffma2(h0b, Wh0[1], ffma2(h1b, Wh1[1], Bb[1]))));
        u64 gG = ffma2(a0b, Wi0[2], ffma2(a1b, Wi1[2], ffma2(h0b, Wh0[2], ffma2(h1b, Wh1[2], Bb[2]))));
        u64 gO = ffma2(a0b, Wi0[3], ffma2(a1b, Wi1[3], ffma2(h0b, Wh0[3], ffma2(h1b, Wh1[3], Bb[3]))));
        float t0, t1;
        funpack(gI, t0, t1); u64 tI = fpack(ftanh(t0), ftanh(t1));
        funpack(gF, t0, t1); u64 tF = fpack(ftanh(t0), ftanh(t1));
        funpack(gG, t0, t1); u64 tG = fpack(ftanh(t0), ftanh(t1));
        funpack(gO, t0, t1); u64 tO = fpack(ftanh(t0), ftanh(t1));
        u64 iP = ffma2(tI, H2, H2);
        u64 fP = ffma2(tF, H2, H2);
        u64 oP = ffma2(tO, H2, H2);
        cn = ffma2(fP, cm, fmul2(iP, tG));
        funpack(cn, t0, t1);
        u64 tC = fpack(ftanh(t0), ftanh(t1));
        return fmul2(oP, tC);
    };

    auto step3 = [&]() -> float {   // consumes (p20,p21) = h2(u-2), updates h3/c3
        u64 a0b = fpack(p20, p20), a1b = fpack(p21, p21);
        u64 h3b = fpack(h3, h3);
        u64 gA = ffma2(a0b, P3wi0A, ffma2(a1b, P3wi1A, ffma2(h3b, P3whA, P3bA)));
        u64 gB = ffma2(a0b, P3wi0B, ffma2(a1b, P3wi1B, ffma2(h3b, P3whB, P3bB)));
        float vi, vf, vg, vo;
        funpack(gA, vi, vf);
        funpack(gB, vg, vo);
        float si = fmaf(ftanh(vi), 0.5f, 0.5f);
        float sf = fmaf(ftanh(vf), 0.5f, 0.5f);
        float tg = ftanh(vg);
        float so = fmaf(ftanh(vo), 0.5f, 0.5f);
        c3 = fmaf(sf, c3, si * tg);
        h3 = so * ftanh(c3);
        return h3 * m30;
    };

    const float* xp = x + e;
    float* op = out + e;
    const long long Bs = (long long)B;
    const unsigned FULL = 0xffffffffu;

    // ---- prologue u = 0 ----
    {
        float xcur = xp[0];
        float a0 = role ? rin0 : xcur;
        float a1 = rin1;
        u64 cn; u64 hn = stepM(a0, a1, cn);
        if (role == 0) { cm = cn; funpack(hn, hm0, hm1); }   // only layer1 commits
        float s0 = __shfl_xor_sync(FULL, hm0, 1);
        float s1 = __shfl_xor_sync(FULL, hm1, 1);
        rin0 = s0; rin1 = s1;                                // B gets h1(0)
    }
    // ---- prologue u = 1 ----
    {
        float xcur = xp[Bs];
        float a0 = role ? rin0 : xcur;
        float a1 = rin1;
        u64 cn; u64 hn = stepM(a0, a1, cn);
        cm = cn; funpack(hn, hm0, hm1);                      // both commit
        float s0 = __shfl_xor_sync(FULL, hm0, 1);
        float s1 = __shfl_xor_sync(FULL, hm1, 1);
        p20 = role ? hm0 : s0;                               // h2(0)
        p21 = role ? hm1 : s1;
        rin0 = s0; rin1 = s1;                                // B gets h1(1)
    }

    // ---- steady state: u = 2 .. T+1 ----
    // lane role0: layer1(u) [clamped x for u>=T]; lane role1: layer2(u-1);
    // both: layer3(u-2) from p2; role0 stores row u-2.
    float xa = xp[2 * Bs], xb = xp[3 * Bs], xc = xp[4 * Bs], xd = xp[5 * Bs];

#define V4_ITER(XREG, OFF)                                                     \
    {                                                                          \
        const int uu = u + (OFF);                                              \
        float a0 = role ? rin0 : XREG;                                         \
        float a1 = rin1;                                                       \
        int nidx = (uu + 4 < T) ? (uu + 4) : (T - 1);                          \
        float nx = xp[(long long)nidx * Bs];                                   \
        u64 cn; u64 hn = stepM(a0, a1, cn);                                    \
        cm = cn; funpack(hn, hm0, hm1);                                        \
        float s0 = __shfl_xor_sync(FULL, hm0, 1);                              \
        float s1 = __shfl_xor_sync(FULL, hm1, 1);                              \
        float yo = step3();                                                    \
        if (role == 0) op[(long long)(uu - 2) * Bs] = yo;                      \
        p20 = role ? hm0 : s0;                                                 \
        p21 = role ? hm1 : s1;                                                 \
        rin0 = s0; rin1 = s1;                                                  \
        XREG = nx;                                                             \
    }

    int u = 2;
    const int UEND = T + 2;                     // exclusive; T iters total
    for (; u + 3 < UEND; u += 4) {
        V4_ITER(xa, 0)
        V4_ITER(xb, 1)
        V4_ITER(xc, 2)
        V4_ITER(xd, 3)
    }
    for (; u < UEND; ++u) {
        float a0 = role ? rin0 : xa;
        float a1 = rin1;
        u64 cn; u64 hn = stepM(a0, a1, cn);
        cm = cn; funpack(hn, hm0, hm1);
        float s0 = __shfl_xor_sync(FULL, hm0, 1);
        float s1 = __shfl_xor_sync(FULL, hm1, 1);
        float yo = step3();
        if (role == 0) op[(long long)(u - 2) * Bs] = yo;
        p20 = role ? hm0 : s0;
        p21 = role ? hm1 : s1;
        rin0 = s0; rin1 = s1;
        xa = xb; xb = xc; xc = xd;
    }
#undef V4_ITER
}

extern "C" void kernel_launch(void* const* d_in, const int* in_sizes, int n_in,
                              void* d_out, int out_size)
{
    const float* x    = (const float*)d_in[0];
    const float* W1ih = (const float*)d_in[1];
    const float* W1hh = (const float*)d_in[2];
    const float* b1   = (const float*)d_in[3];
    const float* m1   = (const float*)d_in[4];
    const float* W2ih = (const float*)d_in[5];
    const float* W2hh = (const float*)d_in[6];
    const float* b2   = (const float*)d_in[7];
    const float* m2   = (const float*)d_in[8];
    const float* W3ih = (const float*)d_in[9];
    const float* W3hh = (const float*)d_in[10];
    const float* b3   = (const float*)d_in[11];
    const float* m3   = (const float*)d_in[12];

    int B = in_sizes[12];            // m3 is [B]
    int T = in_sizes[0] / B;         // x is [T, B, 1]

    // 2 threads per element; 128-thread blocks (4 warps -> 1 per SMSP);
    // grid = 2B/128 = 128 blocks -> 512 warps over 512 SMSPs.
    int threads = 128;
    int blocks = (2 * B + threads - 1) / threads;
    vdlstm_v4_kernel<<<blocks, threads>>>(x, W1ih, W1hh, b1, m1,
                                          W2ih, W2hh, b2, m2,
                                          W3ih, W3hh, b3, m3,
                                          (float*)d_out, T, B);
}

// round 9
// speedup vs baseline: 1.1898x; 1.0147x over previous
#include <cuda_runtime.h>

// VDDecoder: 3-layer LSTM stack (H=2,2,1), locked dropout between layers.
// Lane-pair split (even lane = layer1, odd lane = layer2, uniform stream;
// layer3 redundant on both lanes). R9: iteration body fused and PHASE-GROUPED:
//   A) all gate ffma2s (main layer + layer3)   B) all 12 gate tanhs
//   C) scalar sigmoid-fma + cell updates       D) 3 cell tanhs
//   E) h, shfl, store
// so MUFU latencies pipeline instead of serializing.

typedef unsigned long long u64;

__device__ __forceinline__ float ftanh(float x) {
    float r; asm("tanh.approx.f32 %0, %1;" : "=f"(r) : "f"(x)); return r;
}
__device__ __forceinline__ u64 fpack(float lo, float hi) {
    u64 d; asm("mov.b64 %0, {%1, %2};" : "=l"(d) : "f"(lo), "f"(hi)); return d;
}
__device__ __forceinline__ u64 fpack2(float v) { return fpack(v, v); }
__device__ __forceinline__ void funpack(u64 v, float& lo, float& hi) {
    asm("mov.b64 {%0, %1}, %2;" : "=f"(lo), "=f"(hi) : "l"(v));
}
__device__ __forceinline__ u64 ffma2(u64 a, u64 b, u64 c) {
    u64 d; asm("fma.rn.f32x2 %0, %1, %2, %3;" : "=l"(d) : "l"(a), "l"(b), "l"(c)); return d;
}

extern "C" __global__ void __launch_bounds__(128, 1)
vdlstm_v5_kernel(const float* __restrict__ x,
                 const float* __restrict__ W1ih, const float* __restrict__ W1hh,
                 const float* __restrict__ b1,   const float* __restrict__ m1,
                 const float* __restrict__ W2ih, const float* __restrict__ W2hh,
                 const float* __restrict__ b2,   const float* __restrict__ m2,
                 const float* __restrict__ W3ih, const float* __restrict__ W3hh,
                 const float* __restrict__ b3,   const float* __restrict__ m3,
                 float* __restrict__ out, int T, int B)
{
    const int tid  = threadIdx.x;
    const int role = tid & 1;                       // 0 = layer1 lane, 1 = layer2 lane
    const int e    = blockIdx.x * (blockDim.x >> 1) + (tid >> 1);
    if (e >= B) return;

    // ---- uniform main-LSTM weights (H=2, inputs a0,a1); values differ per role ----
    u64 Wi0[4], Wi1[4], Wh0[4], Wh1[4], Bb[4];
    if (role == 0) {
#pragma unroll
        for (int p = 0; p < 4; p++) {
            float s = (p == 2) ? 1.0f : 0.5f;
            int r0 = 2 * p, r1 = 2 * p + 1;
            Wi0[p] = fpack(W1ih[r0] * s,          W1ih[r1] * s);
            Wi1[p] = fpack(0.f, 0.f);
            Wh0[p] = fpack(W1hh[2 * r0 + 0] * s,  W1hh[2 * r1 + 0] * s);
            Wh1[p] = fpack(W1hh[2 * r0 + 1] * s,  W1hh[2 * r1 + 1] * s);
            Bb[p]  = fpack(b1[r0] * s,            b1[r1] * s);
        }
    } else {
        float m10 = m1[2 * e + 0], m11 = m1[2 * e + 1];
#pragma unroll
        for (int p = 0; p < 4; p++) {
            float s = (p == 2) ? 1.0f : 0.5f;
            int r0 = 2 * p, r1 = 2 * p + 1;
            Wi0[p] = fpack(W2ih[2 * r0 + 0] * s * m10, W2ih[2 * r1 + 0] * s * m10);
            Wi1[p] = fpack(W2ih[2 * r0 + 1] * s * m11, W2ih[2 * r1 + 1] * s * m11);
            Wh0[p] = fpack(W2hh[2 * r0 + 0] * s,       W2hh[2 * r1 + 0] * s);
            Wh1[p] = fpack(W2hh[2 * r0 + 1] * s,       W2hh[2 * r1 + 1] * s);
            Bb[p]  = fpack(b2[r0] * s,                 b2[r1] * s);
        }
    }

    // ---- layer3 weights (both lanes; m2 folded). pairs A=(i,f), B=(g,o) ----
    const float m20 = m2[2 * e + 0], m21 = m2[2 * e + 1];
    const float m30 = m3[e];
    u64 P3wi0A = fpack(W3ih[0] * 0.5f * m20, W3ih[2] * 0.5f * m20);
    u64 P3wi1A = fpack(W3ih[1] * 0.5f * m21, W3ih[3] * 0.5f * m21);
    u64 P3whA  = fpack(W3hh[0] * 0.5f,       W3hh[1] * 0.5f);
    u64 P3bA   = fpack(b3[0] * 0.5f,         b3[1] * 0.5f);
    u64 P3wi0B = fpack(W3ih[4] * m20,        W3ih[6] * 0.5f * m20);
    u64 P3wi1B = fpack(W3ih[5] * m21,        W3ih[7] * 0.5f * m21);
    u64 P3whB  = fpack(W3hh[2],              W3hh[3] * 0.5f);
    u64 P3bB   = fpack(b3[2],                b3[3] * 0.5f);

    // ---- state (all scalar) ----
    float hm0 = 0.f, hm1 = 0.f, cm0 = 0.f, cm1 = 0.f;   // this lane's layer
    float h3 = 0.f,  c3 = 0.f;                          // layer3 (redundant)
    float p20 = 0.f, p21 = 0.f;                         // delayed h2
    float rin0 = 0.f, rin1 = 0.f;                       // partner h pair

    // prologue-only main step (not perf critical)
    auto mainStep = [&](float a0, float a1, float& nh0, float& nh1, float& nc0, float& nc1) {
        u64 a0b = fpack2(a0), a1b = fpack2(a1), h0b = fpack2(hm0), h1b = fpack2(hm1);
        u64 gI = ffma2(a0b, Wi0[0], ffma2(a1b, Wi1[0], ffma2(h0b, Wh0[0], ffma2(h1b, Wh1[0], Bb[0]))));
        u64 gF = ffma2(a0b, Wi0[1], ffma2(a1b, Wi1[1], ffma2(h0b, Wh0[1], ffma2(h1b, Wh1[1], Bb[1]))));
        u64 gG = ffma2(a0b, Wi0[2], ffma2(a1b, Wi1[2], ffma2(h0b, Wh0[2], ffma2(h1b, Wh1[2], Bb[2]))));
        u64 gO = ffma2(a0b, Wi0[3], ffma2(a1b, Wi1[3], ffma2(h0b, Wh0[3], ffma2(h1b, Wh1[3], Bb[3]))));
        float gi0, gi1, gf0, gf1, gg0, gg1, go0, go1;
        funpack(gI, gi0, gi1); funpack(gF, gf0, gf1);
        funpack(gG, gg0, gg1); funpack(gO, go0, go1);
        float i0 = fmaf(ftanh(gi0), 0.5f, 0.5f), i1 = fmaf(ftanh(gi1), 0.5f, 0.5f);
        float f0 = fmaf(ftanh(gf0), 0.5f, 0.5f), f1 = fmaf(ftanh(gf1), 0.5f, 0.5f);
        float t0 = ftanh(gg0), t1 = ftanh(gg1);
        float o0 = fmaf(ftanh(go0), 0.5f, 0.5f), o1 = fmaf(ftanh(go1), 0.5f, 0.5f);
        nc0 = fmaf(f0, cm0, i0 * t0);
        nc1 = fmaf(f1, cm1, i1 * t1);
        nh0 = o0 * ftanh(nc0);
        nh1 = o1 * ftanh(nc1);
    };

    const float* xp = x + e;
    float* op = out + e;
    const long long Bs = (long long)B;
    const unsigned FULL = 0xffffffffu;

    // ---- prologue u = 0 ----
    {
        float xcur = xp[0];
        float a0 = role ? rin0 : xcur, a1 = rin1;
        float nh0, nh1, nc0, nc1;
        mainStep(a0, a1, nh0, nh1, nc0, nc1);
        if (role == 0) { hm0 = nh0; hm1 = nh1; cm0 = nc0; cm1 = nc1; }
        rin0 = __shfl_xor_sync(FULL, hm0, 1);
        rin1 = __shfl_xor_sync(FULL, hm1, 1);
    }
    // ---- prologue u = 1 ----
    {
        float xcur = xp[Bs];
        float a0 = role ? rin0 : xcur, a1 = rin1;
        float nh0, nh1, nc0, nc1;
        mainStep(a0, a1, nh0, nh1, nc0, nc1);
        hm0 = nh0; hm1 = nh1; cm0 = nc0; cm1 = nc1;
        float s0 = __shfl_xor_sync(FULL, hm0, 1);
        float s1 = __shfl_xor_sync(FULL, hm1, 1);
        p20 = role ? hm0 : s0;    // h2(0)
        p21 = role ? hm1 : s1;
        rin0 = s0; rin1 = s1;     // h1(1) for role1
    }

    // ---- steady state: u = 2 .. T+1, phase-grouped fused body ----
    float xa = xp[2 * Bs], xb = xp[3 * Bs], xc = xp[4 * Bs], xd = xp[5 * Bs];

#define V5_ITER(XREG, OFF)                                                     \
    {                                                                          \
        const int uu = u + (OFF);                                              \
        float a0 = role ? rin0 : XREG;                                         \
        float a1 = rin1;                                                       \
        int nidx = (uu + 4 < T) ? (uu + 4) : (T - 1);                          \
        float nx = xp[(long long)nidx * Bs];                                   \
        /* Phase A: all gate pre-activations */                                \
        u64 a0b = fpack2(a0), a1b = fpack2(a1);                                \
        u64 h0b = fpack2(hm0), h1b = fpack2(hm1);                              \
        u64 p0b = fpack2(p20), p1b = fpack2(p21), h3b = fpack2(h3);            \
        u64 gI = ffma2(a0b, Wi0[0], ffma2(a1b, Wi1[0], ffma2(h0b, Wh0[0], ffma2(h1b, Wh1[0], Bb[0])))); \
        u64 gF = ffma2(a0b, Wi0[1], ffma2(a1b, Wi1[1], ffma2(h0b, Wh0[1], ffma2(h1b, Wh1[1], Bb[1])))); \
        u64 gG = ffma2(a0b, Wi0[2], ffma2(a1b, Wi1[2], ffma2(h0b, Wh0[2], ffma2(h1b, Wh1[2], Bb[2])))); \
        u64 gO = ffma2(a0b, Wi0[3], ffma2(a1b, Wi1[3], ffma2(h0b, Wh0[3], ffma2(h1b, Wh1[3], Bb[3])))); \
        u64 gA = ffma2(p0b, P3wi0A, ffma2(p1b, P3wi1A, ffma2(h3b, P3whA, P3bA))); \
        u64 gB = ffma2(p0b, P3wi0B, ffma2(p1b, P3wi1B, ffma2(h3b, P3whB, P3bB))); \
        /* Phase B: all 12 gate tanhs */                                       \
        float gi0, gi1, gf0, gf1, gg0, gg1, go0, go1, vi, vf, vg, vo;          \
        funpack(gI, gi0, gi1); funpack(gF, gf0, gf1);                          \
        funpack(gG, gg0, gg1); funpack(gO, go0, go1);                          \
        funpack(gA, vi, vf);   funpack(gB, vg, vo);                            \
        float ti0 = ftanh(gi0), ti1 = ftanh(gi1);                              \
        float tf0 = ftanh(gf0), tf1 = ftanh(gf1);                              \
        float tg0 = ftanh(gg0), tg1 = ftanh(gg1);                              \
        float to0 = ftanh(go0), to1 = ftanh(go1);                              \
        float tvi = ftanh(vi), tvf = ftanh(vf);                                \
        float tvg = ftanh(vg), tvo = ftanh(vo);                                \
        /* Phase C: sigmoids + cell updates (scalar) */                        \
        float i0 = fmaf(ti0, 0.5f, 0.5f), i1 = fmaf(ti1, 0.5f, 0.5f);          \
        float f0 = fmaf(tf0, 0.5f, 0.5f), f1 = fmaf(tf1, 0.5f, 0.5f);          \
        float o0 = fmaf(to0, 0.5f, 0.5f), o1 = fmaf(to1, 0.5f, 0.5f);          \
        float si = fmaf(tvi, 0.5f, 0.5f), sf = fmaf(tvf, 0.5f, 0.5f);          \
        float so = fmaf(tvo, 0.5f, 0.5f);                                      \
        cm0 = fmaf(f0, cm0, i0 * tg0);                                         \
        cm1 = fmaf(f1, cm1, i1 * tg1);                                         \
        c3  = fmaf(sf, c3, si * tvg);                                          \
        /* Phase D: cell tanhs */                                              \
        float tc0 = ftanh(cm0), tc1 = ftanh(cm1), tc3 = ftanh(c3);             \
        /* Phase E: h, shfl, store */                                          \
        hm0 = o0 * tc0; hm1 = o1 * tc1;                                        \
        float s0 = __shfl_xor_sync(FULL, hm0, 1);                              \
        float s1 = __shfl_xor_sync(FULL, hm1, 1);                              \
        h3 = so * tc3;                                                         \
        if (role == 0) op[(long long)(uu - 2) * Bs] = h3 * m30;                \
        p20 = role ? hm0 : s0;                                                 \
        p21 = role ? hm1 : s1;                                                 \
        rin0 = s0; rin1 = s1;                                                  \
        XREG = nx;                                                             \
    }

    int u = 2;
    const int UEND = T + 2;                 // exclusive; emits rows 0..T-1
    for (; u + 3 < UEND; u += 4) {
        V5_ITER(xa, 0)
        V5_ITER(xb, 1)
        V5_ITER(xc, 2)
        V5_ITER(xd, 3)
    }
    for (; u < UEND; ++u) {
        V5_ITER(xa, 0)
        xa = xb; xb = xc; xc = xd;
    }
#undef V5_ITER
}

extern "C" void kernel_launch(void* const* d_in, const int* in_sizes, int n_in,
                              void* d_out, int out_size)
{
    const float* x    = (const float*)d_in[0];
    const float* W1ih = (const float*)d_in[1];
    const float* W1hh = (const float*)d_in[2];
    const float* b1   = (const float*)d_in[3];
    const float* m1   = (const float*)d_in[4];
    const float* W2ih = (const float*)d_in[5];
    const float* W2hh = (const float*)d_in[6];
    const float* b2   = (const float*)d_in[7];
    const float* m2   = (const float*)d_in[8];
    const float* W3ih = (const float*)d_in[9];
    const float* W3hh = (const float*)d_in[10];
    const float* b3   = (const float*)d_in[11];
    const float* m3   = (const float*)d_in[12];

    int B = in_sizes[12];            // m3 is [B]
    int T = in_sizes[0] / B;         // x is [T, B, 1]

    // 2 threads per element; 128-thread blocks -> 512 warps over ~512 SMSPs.
    int threads = 128;
    int blocks = (2 * B + threads - 1) / threads;
    vdlstm_v5_kernel<<<blocks, threads>>>(x, W1ih, W1hh, b1, m1,
                                          W2ih, W2hh, b2, m2,
                                          W3ih, W3hh, b3, m3,
                                          (float*)d_out, T, B);
}